// round 5
// baseline (speedup 1.0000x reference)
#include <cuda_runtime.h>

#define L_LEN   4096
#define DRAD    32                 // minimum_extrema_distance (fixed for this problem)
#define NTHR    256
#define PER     (L_LEN / NTHR)     // 16
#define NCH     (L_LEN / 32)       // 128 chunks of 32
#define STL     7                  // sparse-table levels over 128 chunks
#define QCAP    256                // queue slots (<= ~127 ever used; 1 slot per thread)

typedef unsigned long long u64;
typedef unsigned int u32;

// dynamic smem layout (bytes):
//   Af   [4096] u64 @ 0       raw keys (leaf scans)
//   pre  [4096] u64 @ 32768   within-chunk inclusive prefix max (aliased as xs float[4096] during build)
//   suf  [4096] u64 @ 65536   within-chunk inclusive suffix max
//   ST [7][128] u64 @ 98304   sparse table over chunk maxima
//   keep [4096] u8  @ 105472
#define OFF_AF   0
#define OFF_PRE  32768
#define OFF_SUF  65536
#define OFF_ST   98304
#define OFF_KEEP 105472
#define SMEM_BYTES (OFF_KEEP + L_LEN)

#define ENC(l, r) (0x80000000u | (u32)(l) | ((u32)(r) << 16))

__device__ __forceinline__ u64 umax64(u64 a, u64 b) { return a > b ? a : b; }

__global__ void __launch_bounds__(NTHR, 1)
extrema_nms_kernel(const float* __restrict__ x, float* __restrict__ out)
{
    extern __shared__ unsigned char sraw[];
    u64* Af  = (u64*)(sraw + OFF_AF);
    u64* pre = (u64*)(sraw + OFF_PRE);
    u64* suf = (u64*)(sraw + OFF_SUF);
    u64 (*ST)[NCH] = (u64 (*)[NCH])(sraw + OFF_ST);
    unsigned char* keep = (unsigned char*)(sraw + OFF_KEEP);
    float* xs = (float*)(sraw + OFF_PRE);        // alias: dead before pre is written

    __shared__ u32 qbuf[QCAP];
    __shared__ int tail;                          // published intervals
    __shared__ int ncons;                         // ended chains
    __shared__ int finished;
    volatile u32* qv = qbuf;
    volatile int* finv = &finished;

    const int tid  = threadIdx.x;
    const int lane = tid & 31;
    const int wid  = tid >> 5;
    const float* xr = x + (size_t)blockIdx.x * L_LEN;

    // ---- init queue + stage x into smem (coalesced float4)
    qbuf[tid] = 0u;
    if (tid == 0) { ncons = 0; finished = 0; qbuf[0] = ENC(0, L_LEN - 1); tail = 1; }
    {
        const float4* xv4 = (const float4*)xr;
        float4* xs4 = (float4*)xs;
        #pragma unroll
        for (int k = 0; k < PER / 4; k++) xs4[tid + k * NTHR] = xv4[tid + k * NTHR];
    }
    __syncthreads();

    // ---- keys: key = (fbits(|x|) << 13) | (L - p): desc |x|, ties -> lower p; unique, nonzero iff extremum
    float xv[PER];
    #pragma unroll
    for (int k = 0; k < PER; k++) {
        int p = tid + k * NTHR;
        float xi = xs[p];
        xv[k] = xi;
        keep[p] = 0;
        // reference pad semantics: dx padded right with 0 (>0 false), left with 0 (<=0 true)
        bool dxr = (p < L_LEN - 1) ? (xs[p + 1] > xi) : false;
        bool dxl = (p > 0)         ? (xi <= xs[p - 1]) : true;
        bool ispos = (xi > 0.0f);
        bool isext = (dxr && dxl && !ispos) || (!dxr && !dxl && ispos);
        u64 key = 0ull;
        if (isext) {
            u32 fb = __float_as_uint(fabsf(xi));
            key = (((u64)fb) << 13) | (u64)(L_LEN - p);
        }
        Af[p] = key;
    }
    __syncthreads();   // Af complete; xs (aliased by pre) dead from here

    // ---- per-chunk prefix/suffix max via warp shuffles (chunk == warp width == 32)
    for (int c = wid; c < NCH; c += NTHR / 32) {
        int base = c << 5;
        u64 v = Af[base + lane];
        u64 pm = v, sm = v;
        #pragma unroll
        for (int s = 1; s < 32; s <<= 1) {
            u64 tu = __shfl_up_sync(0xFFFFFFFFu, pm, s);
            if (lane >= s) pm = umax64(pm, tu);
            u64 td = __shfl_down_sync(0xFFFFFFFFu, sm, s);
            if (lane + s < 32) sm = umax64(sm, td);
        }
        pre[base + lane] = pm;
        suf[base + lane] = sm;
        if (lane == 0) ST[0][c] = sm;    // chunk max
    }
    __syncthreads();

    // ---- sparse table over chunk maxima
    #pragma unroll
    for (int j = 1; j < STL; j++) {
        if (tid < NCH) {
            int w = 1 << (j - 1);
            u64 a = ST[j - 1][tid];
            u64 b = (tid + w < NCH) ? ST[j - 1][tid + w] : 0ull;
            ST[j][tid] = umax64(a, b);
        }
        __syncthreads();
    }

    // ---- async DFS over the static greedy interval tree (no barrier rounds).
    // Thread t owns queue slot t. Chain: keep interval max, continue into left child
    // in-registers, publish right sibling. Termination: tail - ncons == in-flight chains.
    {
        u32 v;
        for (;;) {
            v = qv[tid];
            if (v) break;
            if (*finv) break;
        }
        if (v) {
            int l = (int)(v & 0xFFFFu), r = (int)((v >> 16) & 0x7FFFu);
            for (;;) {
                int cl = l >> 5, cr = r >> 5;
                u64 m;
                if (cl == cr) {                       // in-chunk leaf range: predicated full-chunk scan
                    int base = cl << 5;
                    m = 0ull;
                    #pragma unroll
                    for (int j = 0; j < 32; j++) {
                        int q = base + j;
                        u64 a = Af[q];
                        if (q >= l && q <= r) m = umax64(m, a);
                    }
                } else {
                    m = umax64(suf[l], pre[r]);       // O(1) boundary pieces
                    int a = cl + 1, b = cr - 1;
                    if (a <= b) {                     // full middle chunks: O(1) RMQ
                        int k = 31 - __clz(b - a + 1);
                        m = umax64(m, umax64(ST[k][a], ST[k][b - (1 << k) + 1]));
                    }
                }
                if (!m) break;                        // no extremum in interval
                int p = L_LEN - (int)(m & 0x1FFFull);
                keep[p] = 1;
                int lc = p - (DRAD + 1), rc = p + (DRAD + 1);
                bool hasL = (lc >= l), hasR = (rc <= r);
                if (hasL & hasR) {
                    int t = atomicAdd(&tail, 1);      // bump BEFORE publish (keeps in-flight >= 1)
                    qv[t] = ENC(rc, r);               // payload doubles as ready flag
                    r = lc;
                } else if (hasL) {
                    r = lc;
                } else if (hasR) {
                    l = rc;
                } else break;
            }
            // chain ended
            int c = atomicAdd(&ncons, 1) + 1;
            int T = atomicAdd(&tail, 0);
            if (c == T) *finv = 1;                    // no published-unconsumed, no in-flight
        }
    }
    __syncthreads();

    // ---- output
    float* orow = out + (size_t)blockIdx.x * L_LEN;
    #pragma unroll
    for (int k = 0; k < PER; k++) {
        int p = tid + k * NTHR;
        orow[p] = keep[p] ? xv[k] : 0.0f;
    }
}

extern "C" void kernel_launch(void* const* d_in, const int* in_sizes, int n_in,
                              void* d_out, int out_size)
{
    const float* x = (const float*)d_in[0];
    float* out = (float*)d_out;
    // d_in[1] is minimum_extrema_distance = 32 (compile-time constant DRAD)

    cudaFuncSetAttribute(extrema_nms_kernel,
                         cudaFuncAttributeMaxDynamicSharedMemorySize, SMEM_BYTES);

    int nrows = out_size / L_LEN;   // 128
    extrema_nms_kernel<<<nrows, NTHR, SMEM_BYTES>>>(x, out);
}

// round 6
// speedup vs baseline: 1.2465x; 1.2465x over previous
#include <cuda_runtime.h>

#define L_LEN   4096
#define DRAD    32                 // minimum_extrema_distance (fixed for this problem)
#define NTHR    256
#define PER     (L_LEN / NTHR)     // 16
#define NCH     (L_LEN / 32)       // 128 chunks of 32
#define STL     7                  // sparse-table levels over 128 chunks
#define QCAP    256                // queue slots (<= ~126 ever used; 1 slot per thread)

typedef unsigned long long u64;
typedef unsigned int u32;

// dynamic smem layout (bytes):
//   Af   [4096] u64 @ 0       raw keys (leaf scans)
//   pre  [4096] u64 @ 32768   within-chunk inclusive prefix max
//   suf  [4096] u64 @ 65536   within-chunk inclusive suffix max
//   ST [7][128] u64 @ 98304   sparse table over chunk maxima
//   keep [4096] u8  @ 105472
//   xs   [4096] f32 @ 109568  staged input row
#define OFF_AF   0
#define OFF_PRE  32768
#define OFF_SUF  65536
#define OFF_ST   98304
#define OFF_KEEP 105472
#define OFF_XS   109568
#define SMEM_BYTES (OFF_XS + L_LEN * 4)

#define ENC(l, r) (0x80000000u | (u32)(l) | ((u32)(r) << 16))

__device__ __forceinline__ u64 umax64(u64 a, u64 b) { return a > b ? a : b; }

__global__ void __launch_bounds__(NTHR, 1)
extrema_nms_kernel(const float* __restrict__ x, float* __restrict__ out)
{
    extern __shared__ unsigned char sraw[];
    u64* Af  = (u64*)(sraw + OFF_AF);
    u64* pre = (u64*)(sraw + OFF_PRE);
    u64* suf = (u64*)(sraw + OFF_SUF);
    u64 (*ST)[NCH] = (u64 (*)[NCH])(sraw + OFF_ST);
    unsigned char* keep = (unsigned char*)(sraw + OFF_KEEP);
    float* xs = (float*)(sraw + OFF_XS);

    __shared__ u32 qbuf[QCAP];
    __shared__ int tail;                          // published intervals
    __shared__ int ncons;                         // ended chains
    __shared__ int finished;
    volatile u32* qv = qbuf;
    volatile int* finv = &finished;

    const int tid  = threadIdx.x;
    const int lane = tid & 31;
    const int wid  = tid >> 5;
    const float* xr = x + (size_t)blockIdx.x * L_LEN;

    // ---- init queue + stage x into smem (coalesced float4)
    qbuf[tid] = 0u;
    if (tid == 0) { ncons = 0; finished = 0; qbuf[0] = ENC(0, L_LEN - 1); tail = 1; }
    {
        const float4* xv4 = (const float4*)xr;
        float4* xs4 = (float4*)xs;
        #pragma unroll
        for (int k = 0; k < PER / 4; k++) xs4[tid + k * NTHR] = xv4[tid + k * NTHR];
    }
    __syncthreads();

    // ---- fused build: chunk c = k*8 + wid lives entirely in this warp (lane = offset).
    // Compute key in-register, warp-shuffle prefix/suffix scan, store Af/pre/suf/ST0.
    float xv[PER];
    #pragma unroll
    for (int k = 0; k < PER; k++) {
        int p = tid + k * NTHR;                       // = k*256 + wid*32 + lane
        float xi = xs[p];
        xv[k] = xi;
        keep[p] = 0;
        // reference pad semantics: dx padded right with 0 (>0 false), left with 0 (<=0 true)
        bool dxr = (p < L_LEN - 1) ? (xs[p + 1] > xi) : false;
        bool dxl = (p > 0)         ? (xi <= xs[p - 1]) : true;
        bool ispos = (xi > 0.0f);
        bool isext = (dxr && dxl && !ispos) || (!dxr && !dxl && ispos);
        u64 key = 0ull;
        if (isext) {
            u32 fb = __float_as_uint(fabsf(xi));       // |x| bits: monotone in |x|
            key = (((u64)fb) << 13) | (u64)(L_LEN - p); // desc |x|, ties -> lower p; unique
        }
        Af[p] = key;

        u64 pm = key, sm = key;
        #pragma unroll
        for (int s = 1; s < 32; s <<= 1) {
            u64 tu = __shfl_up_sync(0xFFFFFFFFu, pm, s);
            if (lane >= s) pm = umax64(pm, tu);
            u64 td = __shfl_down_sync(0xFFFFFFFFu, sm, s);
            if (lane + s < 32) sm = umax64(sm, td);
        }
        pre[p] = pm;
        suf[p] = sm;
        if (lane == 31) ST[0][k * 8 + wid] = pm;      // chunk max
    }
    __syncthreads();

    // ---- sparse table over chunk maxima
    #pragma unroll
    for (int j = 1; j < STL; j++) {
        if (tid < NCH) {
            int w = 1 << (j - 1);
            u64 a = ST[j - 1][tid];
            u64 b = (tid + w < NCH) ? ST[j - 1][tid + w] : 0ull;
            ST[j][tid] = umax64(a, b);
        }
        __syncthreads();
    }

    // ---- async DFS over the static greedy interval tree.
    // Thread t owns queue slot t. Chain: keep interval max, continue into left child,
    // publish right sibling (tail bumped BEFORE payload store; payload is the ready flag).
    // Termination: ncons == tail  <=>  all published entries' chains ended  <=>  quiescent.
    {
        u32 v = qv[tid];
        while (!v) {
            if (*finv) break;
            __nanosleep(64);                           // backoff: kill spin pollution
            v = qv[tid];
        }
        if (v) {
            int l = (int)(v & 0xFFFFu), r = (int)((v >> 16) & 0x7FFFu);
            for (;;) {
                int cl = l >> 5, cr = r >> 5;
                u64 m;
                if (cl == cr) {                        // in-chunk leaf: predicated full-chunk scan
                    int base = cl << 5;
                    m = 0ull;
                    #pragma unroll
                    for (int j = 0; j < 32; j++) {
                        int q = base + j;
                        u64 a = Af[q];
                        if (q >= l && q <= r) m = umax64(m, a);
                    }
                } else {
                    m = umax64(suf[l], pre[r]);        // O(1) boundary pieces
                    int a = cl + 1, b = cr - 1;
                    if (a <= b) {                      // full middle chunks: O(1) RMQ
                        int k = 31 - __clz(b - a + 1);
                        m = umax64(m, umax64(ST[k][a], ST[k][b - (1 << k) + 1]));
                    }
                }
                if (!m) break;                         // no extremum in interval
                int p = L_LEN - (int)(m & 0x1FFFull);
                keep[p] = 1;
                int lc = p - (DRAD + 1), rc = p + (DRAD + 1);
                bool hasL = (lc >= l), hasR = (rc <= r);
                if (hasL & hasR) {
                    int t = atomicAdd(&tail, 1);       // bump BEFORE publish (in-flight >= 1)
                    qv[t] = ENC(rc, r);
                    r = lc;
                } else if (hasL) {
                    r = lc;
                } else if (hasR) {
                    l = rc;
                } else break;
            }
            // chain ended
            int c = atomicAdd(&ncons, 1) + 1;
            int T = atomicAdd(&tail, 0);
            if (c == T) *finv = 1;
        }
    }
    __syncthreads();

    // ---- output
    float* orow = out + (size_t)blockIdx.x * L_LEN;
    #pragma unroll
    for (int k = 0; k < PER; k++) {
        int p = tid + k * NTHR;
        orow[p] = keep[p] ? xv[k] : 0.0f;
    }
}

extern "C" void kernel_launch(void* const* d_in, const int* in_sizes, int n_in,
                              void* d_out, int out_size)
{
    const float* x = (const float*)d_in[0];
    float* out = (float*)d_out;
    // d_in[1] is minimum_extrema_distance = 32 (compile-time constant DRAD)

    cudaFuncSetAttribute(extrema_nms_kernel,
                         cudaFuncAttributeMaxDynamicSharedMemorySize, SMEM_BYTES);

    int nrows = out_size / L_LEN;   // 128
    extrema_nms_kernel<<<nrows, NTHR, SMEM_BYTES>>>(x, out);
}

// round 7
// speedup vs baseline: 1.2675x; 1.0169x over previous
#include <cuda_runtime.h>

#define L_LEN   4096
#define DRAD    32                 // minimum_extrema_distance (fixed for this problem)
#define NTHR    512
#define PER     (L_LEN / NTHR)     // 8
#define NCH     (L_LEN / 32)       // 128 chunks of 32
#define NWARP   (NTHR / 32)        // 16
#define STL     7                  // sparse-table levels over 128 chunks
#define QCAP    NTHR               // queue slots (<= ~127 ever used; 1 slot per thread)

typedef unsigned long long u64;
typedef unsigned int u32;

// dynamic smem layout (bytes):
//   Af   [4096] u64 @ 0       raw keys (leaf scans)
//   pre  [4096] u64 @ 32768   within-chunk inclusive prefix max
//   suf  [4096] u64 @ 65536   within-chunk inclusive suffix max
//   ST [7][128] u64 @ 98304   sparse table over chunk maxima
//   keep [4096] u8  @ 105472
//   xs   [4096] f32 @ 109568  staged input row
#define OFF_AF   0
#define OFF_PRE  32768
#define OFF_SUF  65536
#define OFF_ST   98304
#define OFF_KEEP 105472
#define OFF_XS   109568
#define SMEM_BYTES (OFF_XS + L_LEN * 4)

#define ENC(l, r) (0x80000000u | (u32)(l) | ((u32)(r) << 16))

__device__ __forceinline__ u64 umax64(u64 a, u64 b) { return a > b ? a : b; }

__global__ void __launch_bounds__(NTHR, 1)
extrema_nms_kernel(const float* __restrict__ x, float* __restrict__ out)
{
    extern __shared__ unsigned char sraw[];
    u64* Af  = (u64*)(sraw + OFF_AF);
    u64* pre = (u64*)(sraw + OFF_PRE);
    u64* suf = (u64*)(sraw + OFF_SUF);
    u64 (*ST)[NCH] = (u64 (*)[NCH])(sraw + OFF_ST);
    unsigned char* keep = (unsigned char*)(sraw + OFF_KEEP);
    float* xs = (float*)(sraw + OFF_XS);

    __shared__ u32 qbuf[QCAP];
    __shared__ int tail;                          // published intervals
    __shared__ int ncons;                         // ended chains
    __shared__ int finished;
    volatile u32* qv = qbuf;
    volatile int* finv = &finished;

    const int tid  = threadIdx.x;
    const int lane = tid & 31;
    const int wid  = tid >> 5;
    const float* xr = x + (size_t)blockIdx.x * L_LEN;

    // ---- init queue + stage x into smem (coalesced float4)
    qbuf[tid] = 0u;
    if (tid == 0) { ncons = 0; finished = 0; qbuf[0] = ENC(0, L_LEN - 1); tail = 1; }
    {
        const float4* xv4 = (const float4*)xr;
        float4* xs4 = (float4*)xs;
        #pragma unroll
        for (int k = 0; k < PER / 4; k++) xs4[tid + k * NTHR] = xv4[tid + k * NTHR];
    }
    __syncthreads();

    // ---- fused build: chunk c = k*NWARP + wid lives entirely in this warp (lane = offset).
    // Compute key in-register, warp-shuffle prefix/suffix scan, store Af/pre/suf/ST0.
    float xv[PER];
    #pragma unroll
    for (int k = 0; k < PER; k++) {
        int p = tid + k * NTHR;                        // = k*NTHR + wid*32 + lane
        float xi = xs[p];
        xv[k] = xi;
        keep[p] = 0;
        // reference pad semantics: dx padded right with 0 (>0 false), left with 0 (<=0 true)
        bool dxr = (p < L_LEN - 1) ? (xs[p + 1] > xi) : false;
        bool dxl = (p > 0)         ? (xi <= xs[p - 1]) : true;
        bool ispos = (xi > 0.0f);
        bool isext = (dxr && dxl && !ispos) || (!dxr && !dxl && ispos);
        u64 key = 0ull;
        if (isext) {
            u32 fb = __float_as_uint(fabsf(xi));        // |x| bits: monotone in |x|
            key = (((u64)fb) << 13) | (u64)(L_LEN - p); // desc |x|, ties -> lower p; unique
        }
        Af[p] = key;

        u64 pm = key, sm = key;
        #pragma unroll
        for (int s = 1; s < 32; s <<= 1) {
            u64 tu = __shfl_up_sync(0xFFFFFFFFu, pm, s);
            if (lane >= s) pm = umax64(pm, tu);
            u64 td = __shfl_down_sync(0xFFFFFFFFu, sm, s);
            if (lane + s < 32) sm = umax64(sm, td);
        }
        pre[p] = pm;
        suf[p] = sm;
        if (lane == 31) ST[0][k * NWARP + wid] = pm;   // chunk max
    }
    __syncthreads();

    // ---- sparse table over chunk maxima
    #pragma unroll
    for (int j = 1; j < STL; j++) {
        if (tid < NCH) {
            int w = 1 << (j - 1);
            u64 a = ST[j - 1][tid];
            u64 b = (tid + w < NCH) ? ST[j - 1][tid + w] : 0ull;
            ST[j][tid] = umax64(a, b);
        }
        __syncthreads();
    }

    // ---- async DFS over the static greedy interval tree.
    // Thread t owns queue slot t. Chain: keep interval max, continue into left child,
    // publish right sibling (tail bumped BEFORE payload store; payload is the ready flag).
    // Termination: ncons == tail  <=>  all published entries' chains ended  <=>  quiescent.
    {
        u32 v = qv[tid];
        while (!v) {
            if (*finv) break;
            __nanosleep(64);                           // backoff: kill spin pollution
            v = qv[tid];
        }
        if (v) {
            int l = (int)(v & 0xFFFFu), r = (int)((v >> 16) & 0x7FFFu);
            for (;;) {
                int cl = l >> 5, cr = r >> 5;
                u64 m;
                if (cl == cr) {                        // in-chunk leaf: predicated full-chunk scan
                    int base = cl << 5;
                    m = 0ull;
                    #pragma unroll
                    for (int j = 0; j < 32; j++) {
                        int q = base + j;
                        u64 a = Af[q];
                        if (q >= l && q <= r) m = umax64(m, a);
                    }
                } else {
                    m = umax64(suf[l], pre[r]);        // O(1) boundary pieces
                    int a = cl + 1, b = cr - 1;
                    if (a <= b) {                      // full middle chunks: O(1) RMQ
                        int k = 31 - __clz(b - a + 1);
                        m = umax64(m, umax64(ST[k][a], ST[k][b - (1 << k) + 1]));
                    }
                }
                if (!m) break;                         // no extremum in interval
                int p = L_LEN - (int)(m & 0x1FFFull);
                keep[p] = 1;
                int lc = p - (DRAD + 1), rc = p + (DRAD + 1);
                bool hasL = (lc >= l), hasR = (rc <= r);
                if (hasL & hasR) {
                    int t = atomicAdd(&tail, 1);       // bump BEFORE publish (in-flight >= 1)
                    qv[t] = ENC(rc, r);
                    r = lc;
                } else if (hasL) {
                    r = lc;
                } else if (hasR) {
                    l = rc;
                } else break;
            }
            // chain ended
            int c = atomicAdd(&ncons, 1) + 1;
            int T = atomicAdd(&tail, 0);
            if (c == T) *finv = 1;
        }
    }
    __syncthreads();

    // ---- output
    float* orow = out + (size_t)blockIdx.x * L_LEN;
    #pragma unroll
    for (int k = 0; k < PER; k++) {
        int p = tid + k * NTHR;
        orow[p] = keep[p] ? xv[k] : 0.0f;
    }
}

extern "C" void kernel_launch(void* const* d_in, const int* in_sizes, int n_in,
                              void* d_out, int out_size)
{
    const float* x = (const float*)d_in[0];
    float* out = (float*)d_out;
    // d_in[1] is minimum_extrema_distance = 32 (compile-time constant DRAD)

    cudaFuncSetAttribute(extrema_nms_kernel,
                         cudaFuncAttributeMaxDynamicSharedMemorySize, SMEM_BYTES);

    int nrows = out_size / L_LEN;   // 128
    extrema_nms_kernel<<<nrows, NTHR, SMEM_BYTES>>>(x, out);
}

// round 8
// speedup vs baseline: 1.8520x; 1.4611x over previous
#include <cuda_runtime.h>

#define L_LEN   4096
#define DRAD    32                 // minimum_extrema_distance (fixed for this problem)
#define NTHR    512
#define PER     (L_LEN / NTHR)     // 8
#define NCH     (L_LEN / 32)       // 128 chunks of 32
#define NWARP   (NTHR / 32)        // 16
#define STL     7                  // sparse-table levels over 128 chunks
#define QCAP    NTHR               // 1 slot per thread (<= ~127 ever used)

typedef unsigned long long u64;
typedef unsigned int u32;

// dynamic smem layout (bytes):
//   Af   [4096] u64 @ 0       raw keys (leaf scans)
//   pre  [4096] u64 @ 32768   within-chunk inclusive prefix max
//   suf  [4096] u64 @ 65536   within-chunk inclusive suffix max
//   ST [7][128] u64 @ 98304   sparse table over chunk maxima
//   keep [4096] u8  @ 105472
//   xs   [4096] f32 @ 109568  staged input row
#define OFF_AF   0
#define OFF_PRE  32768
#define OFF_SUF  65536
#define OFF_ST   98304
#define OFF_KEEP 105472
#define OFF_XS   109568
#define SMEM_BYTES (OFF_XS + L_LEN * 4)

#define ENC(l, r) (0x80000000u | (u32)(l) | ((u32)(r) << 16))

__device__ __forceinline__ u64 umax64(u64 a, u64 b) { return a > b ? a : b; }

__global__ void __launch_bounds__(NTHR, 1)
extrema_nms_kernel(const float* __restrict__ x, float* __restrict__ out)
{
    extern __shared__ unsigned char sraw[];
    u64* Af  = (u64*)(sraw + OFF_AF);
    u64* pre = (u64*)(sraw + OFF_PRE);
    u64* suf = (u64*)(sraw + OFF_SUF);
    u64 (*ST)[NCH] = (u64 (*)[NCH])(sraw + OFF_ST);
    unsigned char* keep = (unsigned char*)(sraw + OFF_KEEP);
    float* xs = (float*)(sraw + OFF_XS);

    __shared__ u32 qbuf[QCAP];
    __shared__ int tail;                          // published intervals
    __shared__ int ncons;                         // ended chains
    __shared__ int finished;
    volatile u32* qv = qbuf;
    volatile int* finv = &finished;

    const int tid  = threadIdx.x;
    const int lane = tid & 31;
    const int wid  = tid >> 5;
    const float* xr = x + (size_t)blockIdx.x * L_LEN;

    // ---- init queue + stage x into smem (coalesced float4)
    qbuf[tid] = 0u;
    if (tid == 0) { ncons = 0; finished = 0; qbuf[0] = ENC(0, L_LEN - 1); tail = 1; }
    {
        const float4* xv4 = (const float4*)xr;
        float4* xs4 = (float4*)xs;
        #pragma unroll
        for (int k = 0; k < PER / 4; k++) xs4[tid + k * NTHR] = xv4[tid + k * NTHR];
    }
    __syncthreads();

    // ---- fused build: chunk c = k*NWARP + wid lives entirely in this warp (lane = offset).
    float xv[PER];
    #pragma unroll
    for (int k = 0; k < PER; k++) {
        int p = tid + k * NTHR;
        float xi = xs[p];
        xv[k] = xi;
        keep[p] = 0;
        // reference pad semantics: dx padded right with 0 (>0 false), left with 0 (<=0 true)
        bool dxr = (p < L_LEN - 1) ? (xs[p + 1] > xi) : false;
        bool dxl = (p > 0)         ? (xi <= xs[p - 1]) : true;
        bool ispos = (xi > 0.0f);
        bool isext = (dxr && dxl && !ispos) || (!dxr && !dxl && ispos);
        u64 key = 0ull;
        if (isext) {
            u32 fb = __float_as_uint(fabsf(xi));
            key = (((u64)fb) << 13) | (u64)(L_LEN - p);  // desc |x|, ties -> lower p; unique
        }
        Af[p] = key;

        u64 pm = key, sm = key;
        #pragma unroll
        for (int s = 1; s < 32; s <<= 1) {
            u64 tu = __shfl_up_sync(0xFFFFFFFFu, pm, s);
            if (lane >= s) pm = umax64(pm, tu);
            u64 td = __shfl_down_sync(0xFFFFFFFFu, sm, s);
            if (lane + s < 32) sm = umax64(sm, td);
        }
        pre[p] = pm;
        suf[p] = sm;
        if (lane == 31) ST[0][k * NWARP + wid] = pm;     // chunk max
    }
    __syncthreads();

    // ---- sparse table over chunk maxima
    #pragma unroll
    for (int j = 1; j < STL; j++) {
        if (tid < NCH) {
            int w = 1 << (j - 1);
            u64 a = ST[j - 1][tid];
            u64 b = (tid + w < NCH) ? ST[j - 1][tid + w] : 0ull;
            ST[j][tid] = umax64(a, b);
        }
        __syncthreads();
    }

    // ---- async DFS over the static greedy interval tree.
    // Slot s is owned by warp (s % NWARP), lane (s / NWARP): consecutive publishes land in
    // DIFFERENT warps, so concurrently-active chains overlap instead of serializing in one warp.
    // Termination: ncons == tail <=> quiescent (tail bumped before publish; payload = ready flag).
    {
        const int myslot = wid + lane * NWARP;           // bijective slot striping
        u32 v = qv[myslot];
        int spins = 0;
        while (!v) {
            if (*finv) break;
            if (++spins > 4) __nanosleep(32);            // brief hot poll, then backoff
            v = qv[myslot];
        }
        if (v) {
            int l = (int)(v & 0xFFFFu), r = (int)((v >> 16) & 0x7FFFu);
            for (;;) {
                int cl = l >> 5, cr = r >> 5;
                u64 m;
                if (cl == cr) {                          // short in-chunk leaf: exact-range scan
                    m = Af[l];
                    #pragma unroll 4
                    for (int q = l + 1; q <= r; q++) m = umax64(m, Af[q]);
                } else {
                    m = umax64(suf[l], pre[r]);          // O(1) boundary pieces
                    int a = cl + 1, b = cr - 1;
                    if (a <= b) {                        // full middle chunks: O(1) RMQ
                        int k = 31 - __clz(b - a + 1);
                        m = umax64(m, umax64(ST[k][a], ST[k][b - (1 << k) + 1]));
                    }
                }
                if (!m) break;                           // no extremum in interval
                int p = L_LEN - (int)(m & 0x1FFFull);
                int lc = p - (DRAD + 1), rc = p + (DRAD + 1);
                bool hasL = (lc >= l), hasR = (rc <= r);
                if (hasL & hasR) {
                    // publish the NARROWER child ASAP (shallower subtree eats handoff latency),
                    // continue into the wider child locally.
                    int t = atomicAdd(&tail, 1);         // bump BEFORE publish
                    if (lc - l >= r - rc) { qv[t] = ENC(rc, r); keep[p] = 1; r = lc; }
                    else                 { qv[t] = ENC(l, lc); keep[p] = 1; l = rc; }
                } else {
                    keep[p] = 1;
                    if (hasL)      r = lc;
                    else if (hasR) l = rc;
                    else break;
                }
            }
            // chain ended
            int c = atomicAdd(&ncons, 1) + 1;
            int T = atomicAdd(&tail, 0);
            if (c == T) *finv = 1;
        }
    }
    __syncthreads();

    // ---- output
    float* orow = out + (size_t)blockIdx.x * L_LEN;
    #pragma unroll
    for (int k = 0; k < PER; k++) {
        int p = tid + k * NTHR;
        orow[p] = keep[p] ? xv[k] : 0.0f;
    }
}

extern "C" void kernel_launch(void* const* d_in, const int* in_sizes, int n_in,
                              void* d_out, int out_size)
{
    const float* x = (const float*)d_in[0];
    float* out = (float*)d_out;
    // d_in[1] is minimum_extrema_distance = 32 (compile-time constant DRAD)

    cudaFuncSetAttribute(extrema_nms_kernel,
                         cudaFuncAttributeMaxDynamicSharedMemorySize, SMEM_BYTES);

    int nrows = out_size / L_LEN;   // 128
    extrema_nms_kernel<<<nrows, NTHR, SMEM_BYTES>>>(x, out);
}